// round 15
// baseline (speedup 1.0000x reference)
#include <cuda_runtime.h>
#include <cuda_fp16.h>
#include <cstdint>

// SOM layer: coarse fp16 (f16-accumulate) mma.sync GEMM (scores + candidate
// capture) then exact fp32 refinement -> argmin identical to reference.
// R15: sqcvt recoalesced (R8 had silently introduced 64B-stride lane loads,
// 4x uncoalesced); refine split into ballot-score (fast since R14) + flat
// streaming gather. Main GEMM kernel unchanged.

#define DDIM 512
#define MAXN 32768
#define MAXM 4096
#define CAND_CAP 64
#define COARSE_THR 16.0f   // capture margin vs running best
#define PRUNE_THR 10.0f    // refine prune margin vs FINAL best (>= 2*e_max)

#define BM 128
#define BN 256
#define BK 64              // f16 elements per k-tile = 128 bytes/row
#define NTHREADS 256       // 8 warps: 2(m) x 4(n), warp tile 64x64
#define KT (DDIM / BK)     // 8
#define A_STAGE_BYTES (BM * 128)           // 16384
#define B_STAGE_BYTES (BN * 128)           // 32768
#define STAGE_BYTES (A_STAGE_BYTES + B_STAGE_BYTES)  // 49152
#define SMEM_BYTES (2 * STAGE_BYTES)       // 98304

// ---------------- device global scratch (allocation-free rule) --------------
__device__ float g_p2[MAXM];
__device__ float g_z2[MAXN];
__device__ __align__(128) __half g_zh[MAXN * DDIM];   // 32MB
__device__ __align__(128) __half g_ph[MAXM * DDIM];   // 4MB
__device__ float    g_cval[(size_t)MAXN * CAND_CAP];
__device__ int      g_cidx[(size_t)MAXN * CAND_CAP];
__device__ int      g_ccnt[MAXN];
__device__ unsigned g_best[MAXN];
__device__ int      g_widx[MAXN];

// ---------------- helpers ----------------------------------------------------
__device__ __forceinline__ uint32_t smem_u32(const void* p) {
    uint32_t a;
    asm("{ .reg .u64 t; cvta.to.shared.u64 t, %1; cvt.u32.u64 %0, t; }"
        : "=r"(a) : "l"(p));
    return a;
}
__device__ __forceinline__ void cp16(uint32_t dst, const void* src) {
    asm volatile("cp.async.cg.shared.global [%0], [%1], 16;" :: "r"(dst), "l"(src));
}
template <int N> __device__ __forceinline__ void cp_wait() {
    asm volatile("cp.async.wait_group %0;" :: "n"(N));
}
__device__ __forceinline__ void mma_f16acc(uint32_t* c, const uint32_t* a,
                                           uint32_t b0, uint32_t b1) {
    asm volatile(
        "mma.sync.aligned.m16n8k16.row.col.f16.f16.f16.f16 "
        "{%0,%1}, {%2,%3,%4,%5}, {%6,%7}, {%0,%1};"
        : "+r"(c[0]), "+r"(c[1])
        : "r"(a[0]), "r"(a[1]), "r"(a[2]), "r"(a[3]), "r"(b0), "r"(b1));
}
#define LDSM4(r0, r1, r2, r3, addr) \
    asm volatile("ldmatrix.sync.aligned.m8n8.x4.shared.b16 {%0,%1,%2,%3}, [%4];" \
                 : "=r"(r0), "=r"(r1), "=r"(r2), "=r"(r3) : "r"(addr))

// ---------------- fused sum-of-squares + fp16 convert (coalesced) -----------
__device__ __forceinline__ uint32_t pack2_h(float a, float b) {
    __half2 t = __float22half2_rn(make_float2(a, b));
    return *reinterpret_cast<uint32_t*>(&t);
}

__global__ void sqcvt_kernel(const float* __restrict__ x, float* __restrict__ sq,
                             __half* __restrict__ q, int rows, int doInit) {
    int warp = (blockIdx.x * blockDim.x + threadIdx.x) >> 5;
    int lane = threadIdx.x & 31;
    if (warp >= rows) return;
    if (doInit && lane == 1) { g_ccnt[warp] = 0; g_best[warp] = 0x7F800000u; }
    const float4* xr = reinterpret_cast<const float4*>(x) + (size_t)warp * (DDIM / 4);
    uint2* qo = reinterpret_cast<uint2*>(q + (size_t)warp * DDIM);
    float s = 0.f;
#pragma unroll
    for (int i = 0; i < 4; i++) {
        float4 v = xr[lane + i * 32];              // coalesced 512B/warp-load
        s += v.x * v.x + v.y * v.y + v.z * v.z + v.w * v.w;
        uint2 u;
        u.x = pack2_h(v.x, v.y);
        u.y = pack2_h(v.z, v.w);
        qo[lane + i * 32] = u;                     // coalesced 256B/warp-store
    }
#pragma unroll
    for (int o = 16; o; o >>= 1) s += __shfl_xor_sync(0xffffffffu, s, o);
    if (lane == 0) sq[warp] = s;
}

// ---------------- main coarse GEMM + candidate capture ----------------------
// smem per stage: A (128 rows x 128B) then B (256 x 128B); 16B chunk swizzle:
// addr = row*128 + ((chunk ^ (row&7)) << 4)   -- conflict-free for LDSM.
__global__ __launch_bounds__(NTHREADS, 2)
void som_mma_kernel() {
    extern __shared__ __align__(128) unsigned char smem[];
    __shared__ unsigned srow[BM];

    const int tid = threadIdx.x;
    const int wid = tid >> 5;
    const int lane = tid & 31;
    const int wm = wid >> 2;          // 0..1 (M half)
    const int wn = wid & 3;           // 0..3 (N quarter, 64 cols each)
    const int m8 = lane >> 3;         // ldmatrix matrix id 0..3
    const int r8 = lane & 7;
    const int crow = lane >> 2;
    const int qc = lane & 3;

    const int rowBase = blockIdx.x * BM;
    const int colBase = blockIdx.y * BN;

    const __half* gA = g_zh + (size_t)rowBase * DDIM;
    const __half* gB = g_ph + (size_t)colBase * DDIM;

    const uint32_t sbase = smem_u32(smem);

    if (tid < BM) srow[tid] = 0xFFFFFFFFu;

    // cp.async coords: chunk c = tid&7 (16B), base row r0 = tid>>3 (0..31).
    const int cp_c = tid & 7;
    const int cp_r0 = tid >> 3;
    const uint32_t cpA0 = (uint32_t)(cp_r0 * 128 + ((cp_c ^ (cp_r0 & 7)) << 4));
    const uint32_t cpB0 = (uint32_t)(A_STAGE_BYTES + cp_r0 * 128 +
                                     ((cp_c ^ (cp_r0 & 7)) << 4));
    const __half* srcA0 = gA + (size_t)cp_r0 * DDIM + cp_c * 8;
    const __half* srcB0 = gB + (size_t)cp_r0 * DDIM + cp_c * 8;

    // ldmatrix bases; per-kf XOR computed inline (kf compile-time)
    const int rowW = wm * 64 + (m8 & 1) * 8 + r8;
    const int c0a = m8 >> 1;
    const int sxa = rowW & 7;
    const uint32_t aBase = (uint32_t)(rowW * 128);
    const int nW = wn * 64 + (m8 >> 1) * 8 + r8;
    const int c0b = m8 & 1;
    const int sxb = nW & 7;
    const uint32_t bBase = (uint32_t)(A_STAGE_BYTES + nW * 128);

    uint32_t acc[4][8][2];
#pragma unroll
    for (int mi = 0; mi < 4; mi++)
#pragma unroll
        for (int ni = 0; ni < 8; ni++) { acc[mi][ni][0] = 0u; acc[mi][ni][1] = 0u; }

    auto loadStage = [&](int st, int kt) {
        const uint32_t base = sbase + st * STAGE_BYTES;
        const int go = kt * BK;
#pragma unroll
        for (int i = 0; i < 4; i++)
            cp16(base + cpA0 + i * 4096, srcA0 + go + i * (32 * DDIM));
#pragma unroll
        for (int i = 0; i < 8; i++)
            cp16(base + cpB0 + i * 4096, srcB0 + go + i * (32 * DDIM));
        asm volatile("cp.async.commit_group;");
    };

    loadStage(0, 0);

#pragma unroll
    for (int kt = 0; kt < KT; kt++) {
        cp_wait<0>();
        __syncthreads();
        if (kt + 1 < KT) loadStage((kt + 1) & 1, kt + 1);

        const uint32_t stg = sbase + (kt & 1) * STAGE_BYTES;

#pragma unroll
        for (int kf = 0; kf < 4; kf++) {
            const uint32_t aX = (uint32_t)(((kf * 2 + c0a) ^ sxa) << 4);
            const uint32_t bX = (uint32_t)(((kf * 2 + c0b) ^ sxb) << 4);
            uint32_t b[4][4];
#pragma unroll
            for (int p = 0; p < 4; p++)
                LDSM4(b[p][0], b[p][1], b[p][2], b[p][3],
                      stg + bBase + p * 2048 + bX);
#pragma unroll
            for (int mi = 0; mi < 4; mi++) {
                uint32_t a[4];
                LDSM4(a[0], a[1], a[2], a[3], stg + aBase + mi * 2048 + aX);
#pragma unroll
                for (int p = 0; p < 4; p++) {
                    mma_f16acc(acc[mi][2 * p],     a, b[p][0], b[p][1]);
                    mma_f16acc(acc[mi][2 * p + 1], a, b[p][2], b[p][3]);
                }
            }
        }
    }

    // ---- epilogue pass 1: d = z2 - 2*dot + p2, pack back, row min ----------
#pragma unroll
    for (int mi = 0; mi < 4; mi++) {
#pragma unroll
        for (int h = 0; h < 2; h++) {
            int lrow = wm * 64 + mi * 16 + crow + h * 8;
            float z2v = g_z2[rowBase + lrow];
            float tmin = 3.4e38f;
#pragma unroll
            for (int ni = 0; ni < 8; ni++) {
                int gcol = colBase + wn * 64 + ni * 8 + 2 * qc;
                float2 dv = __half22float2(
                    *reinterpret_cast<__half2*>(&acc[mi][ni][h]));
                float d0 = (z2v - 2.0f * dv.x) + __ldg(&g_p2[gcol]);
                float d1 = (z2v - 2.0f * dv.y) + __ldg(&g_p2[gcol + 1]);
                tmin = fminf(tmin, fminf(d0, d1));
                acc[mi][ni][h] = pack2_h(d0, d1);  // f16 round << margins
            }
            atomicMin(&srow[lrow], __float_as_uint(tmin));
        }
    }
    __syncthreads();

    if (tid < BM) atomicMin(&g_best[rowBase + tid], srow[tid]);

    // ---- epilogue pass 2: append candidates within capture margin ----------
#pragma unroll
    for (int mi = 0; mi < 4; mi++) {
#pragma unroll
        for (int h = 0; h < 2; h++) {
            int lrow = wm * 64 + mi * 16 + crow + h * 8;
            int grow = rowBase + lrow;
            float gb = fminf(__uint_as_float(g_best[grow]),
                             __uint_as_float(srow[lrow]));
            float thr = gb + COARSE_THR;
#pragma unroll
            for (int ni = 0; ni < 8; ni++) {
                int gcol = colBase + wn * 64 + ni * 8 + 2 * qc;
                float2 dv = __half22float2(
                    *reinterpret_cast<__half2*>(&acc[mi][ni][h]));
#pragma unroll
                for (int e = 0; e < 2; e++) {
                    float d = (e == 0) ? dv.x : dv.y;
                    if (d < thr) {
                        int slot = atomicAdd(&g_ccnt[grow], 1);
                        if (slot < CAND_CAP) {
                            g_cval[(size_t)grow * CAND_CAP + slot] = d;
                            g_cidx[(size_t)grow * CAND_CAP + slot] = gcol + e;
                        }
                    }
                }
            }
        }
    }
}

// ---------------- exact refinement: lane-parallel prune, winner idx only ----
__global__ void refine_score_kernel(const float* __restrict__ z,
                                    const float* __restrict__ proto, int Mtot) {
    int warp = (blockIdx.x * blockDim.x + threadIdx.x) >> 5;
    int lane = threadIdx.x & 31;
    const int row = warp;

    int cnt = g_ccnt[row];
    float bestD = 3.4e38f;
    int bestI = -1;

    if (cnt <= CAND_CAP) {
        const float gbF = __uint_as_float(g_best[row]);
        const float pthr = gbF + PRUNE_THR;

        // lane-parallel scan: lane k holds candidates k and k+32
        int i1 = -1, i2 = -1;
        bool a1 = false, a2 = false;
        if (lane < cnt) {
            float v = g_cval[(size_t)row * CAND_CAP + lane];
            if (v <= pthr) { a1 = true; i1 = g_cidx[(size_t)row * CAND_CAP + lane]; }
        }
        if (lane + 32 < cnt) {
            float v = g_cval[(size_t)row * CAND_CAP + lane + 32];
            if (v <= pthr) { a2 = true; i2 = g_cidx[(size_t)row * CAND_CAP + lane + 32]; }
        }
        unsigned m1 = __ballot_sync(0xffffffffu, a1);
        unsigned m2 = __ballot_sync(0xffffffffu, a2);
        int ns = __popc(m1) + __popc(m2);

        if (ns == 1) {
            if (m1) bestI = __shfl_sync(0xffffffffu, i1, __ffs(m1) - 1);
            else    bestI = __shfl_sync(0xffffffffu, i2, __ffs(m2) - 1);
        } else {
            const float z2 = g_z2[row];
            float4 zr[4];
#pragma unroll
            for (int i = 0; i < 4; i++)
                zr[i] = reinterpret_cast<const float4*>(z + (size_t)row * DDIM)[i * 32 + lane];
            unsigned mm = m1;
            for (int half = 0; half < 2; half++) {
                while (mm) {
                    int sl = __ffs(mm) - 1;
                    mm &= mm - 1;
                    int c = __shfl_sync(0xffffffffu, half == 0 ? i1 : i2, sl);
                    const float4* pr = reinterpret_cast<const float4*>(proto + (size_t)c * DDIM);
                    float dot = 0.f;
#pragma unroll
                    for (int i = 0; i < 4; i++) {
                        float4 pv = pr[i * 32 + lane];
                        dot += zr[i].x * pv.x + zr[i].y * pv.y + zr[i].z * pv.z + zr[i].w * pv.w;
                    }
#pragma unroll
                    for (int o = 16; o; o >>= 1) dot += __shfl_xor_sync(0xffffffffu, dot, o);
                    float d = (z2 - 2.0f * dot) + __ldg(&g_p2[c]);
                    if (d < bestD || (d == bestD && c < bestI)) { bestD = d; bestI = c; }
                }
                mm = m2;
            }
        }
    } else {
        // overflow (astronomically rare): exact scan of all columns
        const float z2 = g_z2[row];
        float4 zr[4];
#pragma unroll
        for (int i = 0; i < 4; i++)
            zr[i] = reinterpret_cast<const float4*>(z + (size_t)row * DDIM)[i * 32 + lane];
        for (int c = 0; c < Mtot; c++) {
            const float4* pr = reinterpret_cast<const float4*>(proto + (size_t)c * DDIM);
            float dot = 0.f;
#pragma unroll
            for (int i = 0; i < 4; i++) {
                float4 pv = pr[i * 32 + lane];
                dot += zr[i].x * pv.x + zr[i].y * pv.y + zr[i].z * pv.z + zr[i].w * pv.w;
            }
#pragma unroll
            for (int o = 16; o; o >>= 1) dot += __shfl_xor_sync(0xffffffffu, dot, o);
            float d = (z2 - 2.0f * dot) + __ldg(&g_p2[c]);
            if (d < bestD) { bestD = d; bestI = c; }
        }
    }

    if (lane == 0) g_widx[row] = bestI;
}

// ---------------- streaming winner gather + index outputs --------------------
// 128 threads per row, one float4 each. Fully coalesced 64MB write; proto
// reads are L2-resident (4096 rows x 2KB = 8MB).
__global__ void gather_kernel(const float* __restrict__ proto,
                              float* __restrict__ outW,
                              float* __restrict__ outIdxF,
                              int* __restrict__ outIdxI) {
    int gid = blockIdx.x * blockDim.x + threadIdx.x;
    int row = gid >> 7;          // /128
    int c = gid & 127;
    int idx = g_widx[row];
    if (outW) {
        float4 v = reinterpret_cast<const float4*>(proto + (size_t)idx * DDIM)[c];
        reinterpret_cast<float4*>(outW + (size_t)row * DDIM)[c] = v;
    }
    if (c == 0) {
        if (outIdxF) outIdxF[row] = (float)idx;
        if (outIdxI) outIdxI[row] = idx;
    }
}

// ---------------------------------------------------------------------------
extern "C" void kernel_launch(void* const* d_in, const int* in_sizes, int n_in,
                              void* d_out, int out_size) {
    const float* z = (const float*)d_in[0];
    const float* p = (const float*)d_in[1];
    int N = in_sizes[0] / DDIM;
    int M = in_sizes[1] / DDIM;

    float* p2; float* z2; __half* zh; __half* ph;
    cudaGetSymbolAddress((void**)&p2, g_p2);
    cudaGetSymbolAddress((void**)&z2, g_z2);
    cudaGetSymbolAddress((void**)&zh, g_zh);
    cudaGetSymbolAddress((void**)&ph, g_ph);

    sqcvt_kernel<<<(M * 32 + 255) / 256, 256>>>(p, p2, ph, M, 0);
    sqcvt_kernel<<<(N * 32 + 255) / 256, 256>>>(z, z2, zh, N, 1);

    cudaFuncSetAttribute(som_mma_kernel,
                         cudaFuncAttributeMaxDynamicSharedMemorySize, SMEM_BYTES);
    dim3 grid(N / BM, M / BN);   // x = row tiles (fast), y = col tiles
    som_mma_kernel<<<grid, NTHREADS, SMEM_BYTES>>>();

    float* outW = nullptr;
    float* outIdxF = nullptr;
    int* outIdxI = nullptr;
    long long nd = (long long)N * DDIM;
    if ((long long)out_size >= nd) {
        outW = (float*)d_out;
        if ((long long)out_size >= nd + N) outIdxF = (float*)d_out + nd;
    } else if (out_size == N) {
        outIdxI = (int*)d_out;
    }

    refine_score_kernel<<<(N * 32) / 256, 256>>>(z, p, M);
    gather_kernel<<<(N * 128) / 256, 256>>>(p, outW, outIdxF, outIdxI);
}

// round 16
// speedup vs baseline: 1.0217x; 1.0217x over previous
#include <cuda_runtime.h>
#include <cuda_fp16.h>
#include <cstdint>

// SOM layer: coarse fp16 (f16-accumulate) mma.sync GEMM (scores + candidate
// capture) then exact fp32 refinement -> argmin identical to reference.
// R16: recombination of measured-best pieces: R14 fused refine (35.6us,
// split variants regressed twice) + R15 coalesced sqcvt. Main kernel = R11.

#define DDIM 512
#define MAXN 32768
#define MAXM 4096
#define CAND_CAP 64
#define COARSE_THR 16.0f   // capture margin vs running best
#define PRUNE_THR 10.0f    // refine prune margin vs FINAL best (>= 2*e_max)

#define BM 128
#define BN 256
#define BK 64              // f16 elements per k-tile = 128 bytes/row
#define NTHREADS 256       // 8 warps: 2(m) x 4(n), warp tile 64x64
#define KT (DDIM / BK)     // 8
#define A_STAGE_BYTES (BM * 128)           // 16384
#define B_STAGE_BYTES (BN * 128)           // 32768
#define STAGE_BYTES (A_STAGE_BYTES + B_STAGE_BYTES)  // 49152
#define SMEM_BYTES (2 * STAGE_BYTES)       // 98304

// ---------------- device global scratch (allocation-free rule) --------------
__device__ float g_p2[MAXM];
__device__ float g_z2[MAXN];
__device__ __align__(128) __half g_zh[MAXN * DDIM];   // 32MB
__device__ __align__(128) __half g_ph[MAXM * DDIM];   // 4MB
__device__ float    g_cval[(size_t)MAXN * CAND_CAP];
__device__ int      g_cidx[(size_t)MAXN * CAND_CAP];
__device__ int      g_ccnt[MAXN];
__device__ unsigned g_best[MAXN];

// ---------------- helpers ----------------------------------------------------
__device__ __forceinline__ uint32_t smem_u32(const void* p) {
    uint32_t a;
    asm("{ .reg .u64 t; cvta.to.shared.u64 t, %1; cvt.u32.u64 %0, t; }"
        : "=r"(a) : "l"(p));
    return a;
}
__device__ __forceinline__ void cp16(uint32_t dst, const void* src) {
    asm volatile("cp.async.cg.shared.global [%0], [%1], 16;" :: "r"(dst), "l"(src));
}
template <int N> __device__ __forceinline__ void cp_wait() {
    asm volatile("cp.async.wait_group %0;" :: "n"(N));
}
__device__ __forceinline__ void mma_f16acc(uint32_t* c, const uint32_t* a,
                                           uint32_t b0, uint32_t b1) {
    asm volatile(
        "mma.sync.aligned.m16n8k16.row.col.f16.f16.f16.f16 "
        "{%0,%1}, {%2,%3,%4,%5}, {%6,%7}, {%0,%1};"
        : "+r"(c[0]), "+r"(c[1])
        : "r"(a[0]), "r"(a[1]), "r"(a[2]), "r"(a[3]), "r"(b0), "r"(b1));
}
#define LDSM4(r0, r1, r2, r3, addr) \
    asm volatile("ldmatrix.sync.aligned.m8n8.x4.shared.b16 {%0,%1,%2,%3}, [%4];" \
                 : "=r"(r0), "=r"(r1), "=r"(r2), "=r"(r3) : "r"(addr))

// ---------------- fused sum-of-squares + fp16 convert (coalesced) -----------
__device__ __forceinline__ uint32_t pack2_h(float a, float b) {
    __half2 t = __float22half2_rn(make_float2(a, b));
    return *reinterpret_cast<uint32_t*>(&t);
}

__global__ void sqcvt_kernel(const float* __restrict__ x, float* __restrict__ sq,
                             __half* __restrict__ q, int rows, int doInit) {
    int warp = (blockIdx.x * blockDim.x + threadIdx.x) >> 5;
    int lane = threadIdx.x & 31;
    if (warp >= rows) return;
    if (doInit && lane == 1) { g_ccnt[warp] = 0; g_best[warp] = 0x7F800000u; }
    const float4* xr = reinterpret_cast<const float4*>(x) + (size_t)warp * (DDIM / 4);
    uint2* qo = reinterpret_cast<uint2*>(q + (size_t)warp * DDIM);
    float s = 0.f;
#pragma unroll
    for (int i = 0; i < 4; i++) {
        float4 v = xr[lane + i * 32];              // coalesced 512B/warp-load
        s += v.x * v.x + v.y * v.y + v.z * v.z + v.w * v.w;
        uint2 u;
        u.x = pack2_h(v.x, v.y);
        u.y = pack2_h(v.z, v.w);
        qo[lane + i * 32] = u;                     // coalesced 256B/warp-store
    }
#pragma unroll
    for (int o = 16; o; o >>= 1) s += __shfl_xor_sync(0xffffffffu, s, o);
    if (lane == 0) sq[warp] = s;
}

// ---------------- main coarse GEMM + candidate capture ----------------------
// smem per stage: A (128 rows x 128B) then B (256 x 128B); 16B chunk swizzle:
// addr = row*128 + ((chunk ^ (row&7)) << 4)   -- conflict-free for LDSM.
__global__ __launch_bounds__(NTHREADS, 2)
void som_mma_kernel() {
    extern __shared__ __align__(128) unsigned char smem[];
    __shared__ unsigned srow[BM];

    const int tid = threadIdx.x;
    const int wid = tid >> 5;
    const int lane = tid & 31;
    const int wm = wid >> 2;          // 0..1 (M half)
    const int wn = wid & 3;           // 0..3 (N quarter, 64 cols each)
    const int m8 = lane >> 3;         // ldmatrix matrix id 0..3
    const int r8 = lane & 7;
    const int crow = lane >> 2;
    const int qc = lane & 3;

    const int rowBase = blockIdx.x * BM;
    const int colBase = blockIdx.y * BN;

    const __half* gA = g_zh + (size_t)rowBase * DDIM;
    const __half* gB = g_ph + (size_t)colBase * DDIM;

    const uint32_t sbase = smem_u32(smem);

    if (tid < BM) srow[tid] = 0xFFFFFFFFu;

    // cp.async coords: chunk c = tid&7 (16B), base row r0 = tid>>3 (0..31).
    const int cp_c = tid & 7;
    const int cp_r0 = tid >> 3;
    const uint32_t cpA0 = (uint32_t)(cp_r0 * 128 + ((cp_c ^ (cp_r0 & 7)) << 4));
    const uint32_t cpB0 = (uint32_t)(A_STAGE_BYTES + cp_r0 * 128 +
                                     ((cp_c ^ (cp_r0 & 7)) << 4));
    const __half* srcA0 = gA + (size_t)cp_r0 * DDIM + cp_c * 8;
    const __half* srcB0 = gB + (size_t)cp_r0 * DDIM + cp_c * 8;

    // ldmatrix bases; per-kf XOR computed inline (kf compile-time)
    const int rowW = wm * 64 + (m8 & 1) * 8 + r8;
    const int c0a = m8 >> 1;
    const int sxa = rowW & 7;
    const uint32_t aBase = (uint32_t)(rowW * 128);
    const int nW = wn * 64 + (m8 >> 1) * 8 + r8;
    const int c0b = m8 & 1;
    const int sxb = nW & 7;
    const uint32_t bBase = (uint32_t)(A_STAGE_BYTES + nW * 128);

    uint32_t acc[4][8][2];
#pragma unroll
    for (int mi = 0; mi < 4; mi++)
#pragma unroll
        for (int ni = 0; ni < 8; ni++) { acc[mi][ni][0] = 0u; acc[mi][ni][1] = 0u; }

    auto loadStage = [&](int st, int kt) {
        const uint32_t base = sbase + st * STAGE_BYTES;
        const int go = kt * BK;
#pragma unroll
        for (int i = 0; i < 4; i++)
            cp16(base + cpA0 + i * 4096, srcA0 + go + i * (32 * DDIM));
#pragma unroll
        for (int i = 0; i < 8; i++)
            cp16(base + cpB0 + i * 4096, srcB0 + go + i * (32 * DDIM));
        asm volatile("cp.async.commit_group;");
    };

    loadStage(0, 0);

#pragma unroll
    for (int kt = 0; kt < KT; kt++) {
        cp_wait<0>();
        __syncthreads();
        if (kt + 1 < KT) loadStage((kt + 1) & 1, kt + 1);

        const uint32_t stg = sbase + (kt & 1) * STAGE_BYTES;

#pragma unroll
        for (int kf = 0; kf < 4; kf++) {
            const uint32_t aX = (uint32_t)(((kf * 2 + c0a) ^ sxa) << 4);
            const uint32_t bX = (uint32_t)(((kf * 2 + c0b) ^ sxb) << 4);
            uint32_t b[4][4];
#pragma unroll
            for (int p = 0; p < 4; p++)
                LDSM4(b[p][0], b[p][1], b[p][2], b[p][3],
                      stg + bBase + p * 2048 + bX);
#pragma unroll
            for (int mi = 0; mi < 4; mi++) {
                uint32_t a[4];
                LDSM4(a[0], a[1], a[2], a[3], stg + aBase + mi * 2048 + aX);
#pragma unroll
                for (int p = 0; p < 4; p++) {
                    mma_f16acc(acc[mi][2 * p],     a, b[p][0], b[p][1]);
                    mma_f16acc(acc[mi][2 * p + 1], a, b[p][2], b[p][3]);
                }
            }
        }
    }

    // ---- epilogue pass 1: d = z2 - 2*dot + p2, pack back, row min ----------
#pragma unroll
    for (int mi = 0; mi < 4; mi++) {
#pragma unroll
        for (int h = 0; h < 2; h++) {
            int lrow = wm * 64 + mi * 16 + crow + h * 8;
            float z2v = g_z2[rowBase + lrow];
            float tmin = 3.4e38f;
#pragma unroll
            for (int ni = 0; ni < 8; ni++) {
                int gcol = colBase + wn * 64 + ni * 8 + 2 * qc;
                float2 dv = __half22float2(
                    *reinterpret_cast<__half2*>(&acc[mi][ni][h]));
                float d0 = (z2v - 2.0f * dv.x) + __ldg(&g_p2[gcol]);
                float d1 = (z2v - 2.0f * dv.y) + __ldg(&g_p2[gcol + 1]);
                tmin = fminf(tmin, fminf(d0, d1));
                acc[mi][ni][h] = pack2_h(d0, d1);  // f16 round << margins
            }
            atomicMin(&srow[lrow], __float_as_uint(tmin));
        }
    }
    __syncthreads();

    if (tid < BM) atomicMin(&g_best[rowBase + tid], srow[tid]);

    // ---- epilogue pass 2: append candidates within capture margin ----------
#pragma unroll
    for (int mi = 0; mi < 4; mi++) {
#pragma unroll
        for (int h = 0; h < 2; h++) {
            int lrow = wm * 64 + mi * 16 + crow + h * 8;
            int grow = rowBase + lrow;
            float gb = fminf(__uint_as_float(g_best[grow]),
                             __uint_as_float(srow[lrow]));
            float thr = gb + COARSE_THR;
#pragma unroll
            for (int ni = 0; ni < 8; ni++) {
                int gcol = colBase + wn * 64 + ni * 8 + 2 * qc;
                float2 dv = __half22float2(
                    *reinterpret_cast<__half2*>(&acc[mi][ni][h]));
#pragma unroll
                for (int e = 0; e < 2; e++) {
                    float d = (e == 0) ? dv.x : dv.y;
                    if (d < thr) {
                        int slot = atomicAdd(&g_ccnt[grow], 1);
                        if (slot < CAND_CAP) {
                            g_cval[(size_t)grow * CAND_CAP + slot] = d;
                            g_cidx[(size_t)grow * CAND_CAP + slot] = gcol + e;
                        }
                    }
                }
            }
        }
    }
}

// ---------------- exact refinement (lane-parallel prune) + fused gather -----
__global__ void refine_kernel(const float* __restrict__ z,
                              const float* __restrict__ proto, int Mtot,
                              float* __restrict__ outW,
                              float* __restrict__ outIdxF,
                              int* __restrict__ outIdxI) {
    int warp = (blockIdx.x * blockDim.x + threadIdx.x) >> 5;
    int lane = threadIdx.x & 31;
    const int row = warp;

    int cnt = g_ccnt[row];
    float bestD = 3.4e38f;
    int bestI = -1;

    if (cnt <= CAND_CAP) {
        const float gbF = __uint_as_float(g_best[row]);
        const float pthr = gbF + PRUNE_THR;

        // lane-parallel scan: lane k holds candidates k and k+32
        int i1 = -1, i2 = -1;
        bool a1 = false, a2 = false;
        if (lane < cnt) {
            float v = g_cval[(size_t)row * CAND_CAP + lane];
            if (v <= pthr) { a1 = true; i1 = g_cidx[(size_t)row * CAND_CAP + lane]; }
        }
        if (lane + 32 < cnt) {
            float v = g_cval[(size_t)row * CAND_CAP + lane + 32];
            if (v <= pthr) { a2 = true; i2 = g_cidx[(size_t)row * CAND_CAP + lane + 32]; }
        }
        unsigned m1 = __ballot_sync(0xffffffffu, a1);
        unsigned m2 = __ballot_sync(0xffffffffu, a2);
        int ns = __popc(m1) + __popc(m2);

        if (ns == 1) {
            // unique survivor: it is the argmin; no scoring needed
            if (m1) bestI = __shfl_sync(0xffffffffu, i1, __ffs(m1) - 1);
            else    bestI = __shfl_sync(0xffffffffu, i2, __ffs(m2) - 1);
        } else {
            // score each survivor with the exact full-warp dot
            const float z2 = g_z2[row];
            float4 zr[4];
#pragma unroll
            for (int i = 0; i < 4; i++)
                zr[i] = reinterpret_cast<const float4*>(z + (size_t)row * DDIM)[i * 32 + lane];
            unsigned mm = m1;
            for (int half = 0; half < 2; half++) {
                while (mm) {
                    int sl = __ffs(mm) - 1;
                    mm &= mm - 1;
                    int c = __shfl_sync(0xffffffffu, half == 0 ? i1 : i2, sl);
                    const float4* pr = reinterpret_cast<const float4*>(proto + (size_t)c * DDIM);
                    float dot = 0.f;
#pragma unroll
                    for (int i = 0; i < 4; i++) {
                        float4 pv = pr[i * 32 + lane];
                        dot += zr[i].x * pv.x + zr[i].y * pv.y + zr[i].z * pv.z + zr[i].w * pv.w;
                    }
#pragma unroll
                    for (int o = 16; o; o >>= 1) dot += __shfl_xor_sync(0xffffffffu, dot, o);
                    float d = (z2 - 2.0f * dot) + __ldg(&g_p2[c]);
                    if (d < bestD || (d == bestD && c < bestI)) { bestD = d; bestI = c; }
                }
                mm = m2;
            }
        }
    } else {
        // overflow (astronomically rare): exact scan of all columns
        const float z2 = g_z2[row];
        float4 zr[4];
#pragma unroll
        for (int i = 0; i < 4; i++)
            zr[i] = reinterpret_cast<const float4*>(z + (size_t)row * DDIM)[i * 32 + lane];
        for (int c = 0; c < Mtot; c++) {
            const float4* pr = reinterpret_cast<const float4*>(proto + (size_t)c * DDIM);
            float dot = 0.f;
#pragma unroll
            for (int i = 0; i < 4; i++) {
                float4 pv = pr[i * 32 + lane];
                dot += zr[i].x * pv.x + zr[i].y * pv.y + zr[i].z * pv.z + zr[i].w * pv.w;
            }
#pragma unroll
            for (int o = 16; o; o >>= 1) dot += __shfl_xor_sync(0xffffffffu, dot, o);
            float d = (z2 - 2.0f * dot) + __ldg(&g_p2[c]);
            if (d < bestD) { bestD = d; bestI = c; }
        }
    }

    if (lane == 0) {
        if (outIdxF) outIdxF[row] = (float)bestI;
        if (outIdxI) outIdxI[row] = bestI;
    }
    if (outW) {
        const float4* pr = reinterpret_cast<const float4*>(proto + (size_t)bestI * DDIM);
        float4* ow = reinterpret_cast<float4*>(outW + (size_t)row * DDIM);
#pragma unroll
        for (int i = 0; i < 4; i++) ow[i * 32 + lane] = pr[i * 32 + lane];
    }
}

// ---------------------------------------------------------------------------
extern "C" void kernel_launch(void* const* d_in, const int* in_sizes, int n_in,
                              void* d_out, int out_size) {
    const float* z = (const float*)d_in[0];
    const float* p = (const float*)d_in[1];
    int N = in_sizes[0] / DDIM;
    int M = in_sizes[1] / DDIM;

    float* p2; float* z2; __half* zh; __half* ph;
    cudaGetSymbolAddress((void**)&p2, g_p2);
    cudaGetSymbolAddress((void**)&z2, g_z2);
    cudaGetSymbolAddress((void**)&zh, g_zh);
    cudaGetSymbolAddress((void**)&ph, g_ph);

    sqcvt_kernel<<<(M * 32 + 255) / 256, 256>>>(p, p2, ph, M, 0);
    sqcvt_kernel<<<(N * 32 + 255) / 256, 256>>>(z, z2, zh, N, 1);

    cudaFuncSetAttribute(som_mma_kernel,
                         cudaFuncAttributeMaxDynamicSharedMemorySize, SMEM_BYTES);
    dim3 grid(N / BM, M / BN);   // x = row tiles (fast), y = col tiles
    som_mma_kernel<<<grid, NTHREADS, SMEM_BYTES>>>();

    float* outW = nullptr;
    float* outIdxF = nullptr;
    int* outIdxI = nullptr;
    long long nd = (long long)N * DDIM;
    if ((long long)out_size >= nd) {
        outW = (float*)d_out;
        if ((long long)out_size >= nd + N) outIdxF = (float*)d_out + nd;
    } else if (out_size == N) {
        outIdxI = (int*)d_out;
    }

    refine_kernel<<<(N * 32) / 256, 256>>>(z, p, M, outW, outIdxF, outIdxI);
}